// round 9
// baseline (speedup 1.0000x reference)
#include <cuda_runtime.h>

#define TPB 256

__device__ float g_sum = 0.0f;
__device__ unsigned int g_count = 0;

__device__ __forceinline__ float compute_iou(float bx, float by, float bw, float bh,
                                             float lx, float ly, float lw, float lh) {
    const float invS = 1.0f / 7.0f;
    float x1 = bx * invS - bw * 0.5f;
    float y1 = by * invS - bh * 0.5f;
    float x2 = bx * invS + bw * 0.5f;
    float y2 = by * invS + bh * 0.5f;
    float u1 = lx * invS - lw * 0.5f;
    float v1 = ly * invS - lh * 0.5f;
    float u2 = lx * invS + lw * 0.5f;
    float v2 = ly * invS + lh * 0.5f;
    float a1 = (x2 - x1) * (y2 - y1);
    float a2 = (u2 - u1) * (v2 - v1);
    float left   = fmaxf(x1, u1);
    float right  = fminf(x2, u2);
    float top    = fmaxf(y1, v1);
    float bottom = fminf(y2, v2);
    bool valid = (left < right) && (top < bottom);
    float inter = valid ? (right - left) * (bottom - top) : 0.0f;
    float uni = a1 + a2 - inter;
    return valid ? (inter / uni) : 0.0f;
}

__global__ void __launch_bounds__(TPB)
yolo_kernel(const float* __restrict__ predict,
            const float* __restrict__ label,
            int ncells, float invN,
            float* __restrict__ out) {
    const int tid = threadIdx.x;
    int cell = blockIdx.x * TPB + tid;
    float loss = 0.0f;

    if (cell < ncells) {
        const float* pbase = predict + (size_t)cell * 26;
        const float* lbase = label   + (size_t)cell * 26;

        float l4 = __ldg(lbase + 4);
        float p4 = __ldg(pbase + 4);
        float p9 = __ldg(pbase + 9);

        if (l4 == 0.0f) {
            // noobj cell (~96%)
            loss = 0.5f * (p4 * p4 + p9 * p9);
        } else {
            // coord cell (~4%) — float2 streaming, no local arrays, no spills
            const float2* pp = reinterpret_cast<const float2*>(pbase);
            const float2* lp = reinterpret_cast<const float2*>(lbase);

            float2 p01 = __ldg(pp + 0);
            float2 p23 = __ldg(pp + 1);
            float2 p45 = __ldg(pp + 2);
            float2 p67 = __ldg(pp + 3);
            float2 p89 = __ldg(pp + 4);
            float2 l01 = __ldg(lp + 0);
            float2 l23 = __ldg(lp + 1);

            float cls = 0.0f;
#pragma unroll
            for (int j = 5; j < 13; j++) {
                float2 pv = __ldg(pp + j);
                float2 lv = __ldg(lp + j);
                float dx = pv.x - lv.x;
                float dy = pv.y - lv.y;
                cls += dx * dx + dy * dy;
            }

            float iou1 = compute_iou(p01.x, p01.y, p23.x, p23.y,
                                     l01.x, l01.y, l23.x, l23.y);
            float iou2 = compute_iou(p45.y, p67.x, p67.y, p89.x,
                                     l01.x, l01.y, l23.x, l23.y);
            bool pick1 = iou1 > iou2;

            float s0 = pick1 ? p01.x : p45.y;
            float s1 = pick1 ? p01.y : p67.x;
            float s2 = pick1 ? p23.x : p67.y;
            float s3 = pick1 ? p23.y : p89.x;

            float d0 = s0 - l01.x;
            float d1 = s1 - l01.y;
            float d2 = sqrtf(s2) - sqrtf(l23.x);
            float d3 = sqrtf(s3) - sqrtf(l23.y);
            float coord_cell = d0 * d0 + d1 * d1 + d2 * d2 + d3 * d3;

            float c  = pick1 ? p45.x : p89.y;
            float io = pick1 ? iou1  : iou2;
            float dc = c - io;
            float obj_c_cell = dc * dc;

            float other = pick1 ? p89.y : p45.x;
            float noobj_extra = other * other;

            loss = 5.0f * coord_cell + obj_c_cell + 0.5f * noobj_extra + cls;
        }
    }

    // ---- block reduction ----
    __shared__ float sm[TPB / 32];
    float s = loss;
#pragma unroll
    for (int o = 16; o > 0; o >>= 1)
        s += __shfl_down_sync(0xFFFFFFFFu, s, o);
    if ((tid & 31) == 0)
        sm[tid >> 5] = s;
    __syncthreads();
    if (tid < 32) {
        s = (tid < (TPB / 32)) ? sm[tid] : 0.0f;
#pragma unroll
        for (int o = 16; o > 0; o >>= 1)
            s += __shfl_down_sync(0xFFFFFFFFu, s, o);
        if (tid == 0) {
            // One fire-and-forget L2 atomic add of the block sum (release so it
            // is visible before the counter inc), then an acq_rel counter inc.
            // No syncthreads, no broadcast — other warps have already exited.
            asm volatile("red.release.gpu.global.add.f32 [%0], %1;"
                         :: "l"(&g_sum), "f"(s) : "memory");
            unsigned int old;
            asm volatile("atom.acq_rel.gpu.global.inc.u32 %0, [%1], %2;"
                         : "=r"(old)
                         : "l"(&g_count), "r"(gridDim.x - 1)
                         : "memory");
            if (old == gridDim.x - 1) {
                // Last arriver: read total AND reset to 0 in one atomic
                // (state restored for next graph replay).
                float total = atomicExch(&g_sum, 0.0f);
                out[0] = total * invN;
            }
        }
    }
}

extern "C" void kernel_launch(void* const* d_in, const int* in_sizes, int n_in,
                              void* d_out, int out_size) {
    const float* predict = (const float*)d_in[0];
    const float* label   = (const float*)d_in[1];
    float* out = (float*)d_out;

    int total  = in_sizes[0];          // B*7*7*26
    int ncells = total / 26;           // B*49
    int nblocks = (ncells + TPB - 1) / TPB;

    float invN = 49.0f / (float)ncells;  // 1 / batch

    yolo_kernel<<<nblocks, TPB>>>(predict, label, ncells, invN, out);
}

// round 10
// speedup vs baseline: 1.1373x; 1.1373x over previous
#include <cuda_runtime.h>

#define TPB 256
#define MAX_BLOCKS 8192

__device__ float g_partials[MAX_BLOCKS];

__device__ __forceinline__ float compute_iou(float bx, float by, float bw, float bh,
                                             float lx, float ly, float lw, float lh) {
    const float invS = 1.0f / 7.0f;
    float x1 = bx * invS - bw * 0.5f;
    float y1 = by * invS - bh * 0.5f;
    float x2 = bx * invS + bw * 0.5f;
    float y2 = by * invS + bh * 0.5f;
    float u1 = lx * invS - lw * 0.5f;
    float v1 = ly * invS - lh * 0.5f;
    float u2 = lx * invS + lw * 0.5f;
    float v2 = ly * invS + lh * 0.5f;
    float a1 = (x2 - x1) * (y2 - y1);
    float a2 = (u2 - u1) * (v2 - v1);
    float left   = fmaxf(x1, u1);
    float right  = fminf(x2, u2);
    float top    = fmaxf(y1, v1);
    float bottom = fminf(y2, v2);
    bool valid = (left < right) && (top < bottom);
    float inter = valid ? (right - left) * (bottom - top) : 0.0f;
    float uni = a1 + a2 - inter;
    return valid ? (inter / uni) : 0.0f;
}

__global__ void __launch_bounds__(TPB)
yolo_cell_kernel(const float* __restrict__ predict,
                 const float* __restrict__ label,
                 int ncells) {
    int cell = blockIdx.x * blockDim.x + threadIdx.x;
    float loss = 0.0f;

    if (cell < ncells) {
        const float* pbase = predict + (size_t)cell * 26;
        const float* lbase = label   + (size_t)cell * 26;

        float l4 = __ldg(lbase + 4);
        float p4 = __ldg(pbase + 4);
        float p9 = __ldg(pbase + 9);

        if (l4 == 0.0f) {
            // noobj cell (~96%)
            loss = 0.5f * (p4 * p4 + p9 * p9);
        } else {
            // coord cell (~4%) — float2 streaming, no local arrays, no spills
            const float2* pp = reinterpret_cast<const float2*>(pbase);
            const float2* lp = reinterpret_cast<const float2*>(lbase);

            float2 p01 = __ldg(pp + 0);
            float2 p23 = __ldg(pp + 1);
            float2 p45 = __ldg(pp + 2);
            float2 p67 = __ldg(pp + 3);
            float2 p89 = __ldg(pp + 4);
            float2 l01 = __ldg(lp + 0);
            float2 l23 = __ldg(lp + 1);

            float cls = 0.0f;
#pragma unroll
            for (int j = 5; j < 13; j++) {
                float2 pv = __ldg(pp + j);
                float2 lv = __ldg(lp + j);
                float dx = pv.x - lv.x;
                float dy = pv.y - lv.y;
                cls += dx * dx + dy * dy;
            }

            float iou1 = compute_iou(p01.x, p01.y, p23.x, p23.y,
                                     l01.x, l01.y, l23.x, l23.y);
            float iou2 = compute_iou(p45.y, p67.x, p67.y, p89.x,
                                     l01.x, l01.y, l23.x, l23.y);
            bool pick1 = iou1 > iou2;

            float s0 = pick1 ? p01.x : p45.y;
            float s1 = pick1 ? p01.y : p67.x;
            float s2 = pick1 ? p23.x : p67.y;
            float s3 = pick1 ? p23.y : p89.x;

            float d0 = s0 - l01.x;
            float d1 = s1 - l01.y;
            float d2 = sqrtf(s2) - sqrtf(l23.x);
            float d3 = sqrtf(s3) - sqrtf(l23.y);
            float coord_cell = d0 * d0 + d1 * d1 + d2 * d2 + d3 * d3;

            float c  = pick1 ? p45.x : p89.y;
            float io = pick1 ? iou1  : iou2;
            float dc = c - io;
            float obj_c_cell = dc * dc;

            float other = pick1 ? p89.y : p45.x;
            float noobj_extra = other * other;

            loss = 5.0f * coord_cell + obj_c_cell + 0.5f * noobj_extra + cls;
        }
    }

    // ---- block reduction ----
    __shared__ float sm[TPB / 32];
    float s = loss;
#pragma unroll
    for (int o = 16; o > 0; o >>= 1)
        s += __shfl_down_sync(0xFFFFFFFFu, s, o);
    if ((threadIdx.x & 31) == 0)
        sm[threadIdx.x >> 5] = s;
    __syncthreads();
    if (threadIdx.x < 32) {
        s = (threadIdx.x < (TPB / 32)) ? sm[threadIdx.x] : 0.0f;
#pragma unroll
        for (int o = 16; o > 0; o >>= 1)
            s += __shfl_down_sync(0xFFFFFFFFu, s, o);
        if (threadIdx.x == 0) {
            g_partials[blockIdx.x] = s;
            // Publish the partial, then trigger the dependent launch event.
            // When ALL blocks have triggered, the consumer's
            // cudaGridDependencySynchronize() returns and all fenced writes
            // are visible. One thread per block; other warps already done.
            __threadfence();
            cudaTriggerProgrammaticLaunchCompletion();
        }
    }
}

__global__ void yolo_reduce_kernel(float* __restrict__ out, int nblocks, float invN) {
    // Resident early thanks to PDL; parks here until every producer block
    // has stored+fenced its partial and triggered.
    cudaGridDependencySynchronize();

    __shared__ float sm[32];
    int nf4 = nblocks >> 2;
    const float4* p4 = reinterpret_cast<const float4*>(g_partials);
    float s = 0.0f;
    for (int i = threadIdx.x; i < nf4; i += blockDim.x) {
        float4 v = p4[i];
        s += (v.x + v.y) + (v.z + v.w);
    }
    for (int i = (nf4 << 2) + threadIdx.x; i < nblocks; i += blockDim.x)
        s += g_partials[i];
#pragma unroll
    for (int o = 16; o > 0; o >>= 1)
        s += __shfl_down_sync(0xFFFFFFFFu, s, o);
    if ((threadIdx.x & 31) == 0)
        sm[threadIdx.x >> 5] = s;
    __syncthreads();
    if (threadIdx.x < 32) {
        s = (threadIdx.x < (int)(blockDim.x >> 5)) ? sm[threadIdx.x] : 0.0f;
#pragma unroll
        for (int o = 16; o > 0; o >>= 1)
            s += __shfl_down_sync(0xFFFFFFFFu, s, o);
        if (threadIdx.x == 0)
            out[0] = s * invN;
    }
}

extern "C" void kernel_launch(void* const* d_in, const int* in_sizes, int n_in,
                              void* d_out, int out_size) {
    const float* predict = (const float*)d_in[0];
    const float* label   = (const float*)d_in[1];
    float* out = (float*)d_out;

    int total  = in_sizes[0];          // B*7*7*26
    int ncells = total / 26;           // B*49
    int nblocks = (ncells + TPB - 1) / TPB;
    if (nblocks > MAX_BLOCKS) nblocks = MAX_BLOCKS;  // never hit for this shape

    float invN = 49.0f / (float)ncells;  // 1 / batch

    yolo_cell_kernel<<<nblocks, TPB>>>(predict, label, ncells);

    // Dependent reduce: launches concurrently with the producer, synchronizes
    // on the producer's programmatic trigger inside the kernel.
    cudaLaunchConfig_t cfg = {};
    cfg.gridDim  = dim3(1, 1, 1);
    cfg.blockDim = dim3(1024, 1, 1);
    cfg.dynamicSmemBytes = 0;
    cfg.stream = 0;
    cudaLaunchAttribute attr[1];
    attr[0].id = cudaLaunchAttributeProgrammaticStreamSerialization;
    attr[0].val.programmaticStreamSerializationAllowed = 1;
    cfg.attrs = attr;
    cfg.numAttrs = 1;
    cudaLaunchKernelEx(&cfg, yolo_reduce_kernel, out, nblocks, invN);
}

// round 11
// speedup vs baseline: 1.2052x; 1.0597x over previous
#include <cuda_runtime.h>

#define TPB 256

__device__ __forceinline__ float compute_iou(float bx, float by, float bw, float bh,
                                             float lx, float ly, float lw, float lh) {
    const float invS = 1.0f / 7.0f;
    float x1 = bx * invS - bw * 0.5f;
    float y1 = by * invS - bh * 0.5f;
    float x2 = bx * invS + bw * 0.5f;
    float y2 = by * invS + bh * 0.5f;
    float u1 = lx * invS - lw * 0.5f;
    float v1 = ly * invS - lh * 0.5f;
    float u2 = lx * invS + lw * 0.5f;
    float v2 = ly * invS + lh * 0.5f;
    float a1 = (x2 - x1) * (y2 - y1);
    float a2 = (u2 - u1) * (v2 - v1);
    float left   = fmaxf(x1, u1);
    float right  = fminf(x2, u2);
    float top    = fmaxf(y1, v1);
    float bottom = fminf(y2, v2);
    bool valid = (left < right) && (top < bottom);
    float inter = valid ? (right - left) * (bottom - top) : 0.0f;
    float uni = a1 + a2 - inter;
    return valid ? (inter / uni) : 0.0f;
}

__global__ void __launch_bounds__(TPB)
yolo_kernel(const float* __restrict__ predict,
            const float* __restrict__ label,
            int ncells, float invN,
            float* __restrict__ out) {
    const int tid = threadIdx.x;
    int cell = blockIdx.x * TPB + tid;
    float loss = 0.0f;

    if (cell < ncells) {
        const float* pbase = predict + (size_t)cell * 26;
        const float* lbase = label   + (size_t)cell * 26;

        float l4 = __ldg(lbase + 4);
        float p4 = __ldg(pbase + 4);
        float p9 = __ldg(pbase + 9);

        if (l4 == 0.0f) {
            // noobj cell (~96%)
            loss = 0.5f * (p4 * p4 + p9 * p9);
        } else {
            // coord cell (~4%) — float2 streaming, no local arrays, no spills
            const float2* pp = reinterpret_cast<const float2*>(pbase);
            const float2* lp = reinterpret_cast<const float2*>(lbase);

            float2 p01 = __ldg(pp + 0);
            float2 p23 = __ldg(pp + 1);
            float2 p45 = __ldg(pp + 2);
            float2 p67 = __ldg(pp + 3);
            float2 p89 = __ldg(pp + 4);
            float2 l01 = __ldg(lp + 0);
            float2 l23 = __ldg(lp + 1);

            float cls = 0.0f;
#pragma unroll
            for (int j = 5; j < 13; j++) {
                float2 pv = __ldg(pp + j);
                float2 lv = __ldg(lp + j);
                float dx = pv.x - lv.x;
                float dy = pv.y - lv.y;
                cls += dx * dx + dy * dy;
            }

            float iou1 = compute_iou(p01.x, p01.y, p23.x, p23.y,
                                     l01.x, l01.y, l23.x, l23.y);
            float iou2 = compute_iou(p45.y, p67.x, p67.y, p89.x,
                                     l01.x, l01.y, l23.x, l23.y);
            bool pick1 = iou1 > iou2;

            float s0 = pick1 ? p01.x : p45.y;
            float s1 = pick1 ? p01.y : p67.x;
            float s2 = pick1 ? p23.x : p67.y;
            float s3 = pick1 ? p23.y : p89.x;

            float d0 = s0 - l01.x;
            float d1 = s1 - l01.y;
            float d2 = sqrtf(s2) - sqrtf(l23.x);
            float d3 = sqrtf(s3) - sqrtf(l23.y);
            float coord_cell = d0 * d0 + d1 * d1 + d2 * d2 + d3 * d3;

            float c  = pick1 ? p45.x : p89.y;
            float io = pick1 ? iou1  : iou2;
            float dc = c - io;
            float obj_c_cell = dc * dc;

            float other = pick1 ? p89.y : p45.x;
            float noobj_extra = other * other;

            loss = 5.0f * coord_cell + obj_c_cell + 0.5f * noobj_extra + cls;
        }
    }

    // ---- block reduction ----
    __shared__ float sm[TPB / 32];
    float s = loss;
#pragma unroll
    for (int o = 16; o > 0; o >>= 1)
        s += __shfl_down_sync(0xFFFFFFFFu, s, o);
    if ((tid & 31) == 0)
        sm[tid >> 5] = s;
    __syncthreads();
    if (tid < 32) {
        s = (tid < (TPB / 32)) ? sm[tid] : 0.0f;
#pragma unroll
        for (int o = 16; o > 0; o >>= 1)
            s += __shfl_down_sync(0xFFFFFFFFu, s, o);
        if (tid == 0) {
            // Single fire-and-forget no-return reduction into out[0]
            // (pre-zeroed by the memset graph node). No counter, no fence,
            // no result wait — REDG costs ~1 cycle issue per block.
            float contrib = s * invN;
            asm volatile("red.relaxed.gpu.global.add.f32 [%0], %1;"
                         :: "l"(out), "f"(contrib) : "memory");
        }
    }
}

extern "C" void kernel_launch(void* const* d_in, const int* in_sizes, int n_in,
                              void* d_out, int out_size) {
    const float* predict = (const float*)d_in[0];
    const float* label   = (const float*)d_in[1];
    float* out = (float*)d_out;

    int total  = in_sizes[0];          // B*7*7*26
    int ncells = total / 26;           // B*49
    int nblocks = (ncells + TPB - 1) / TPB;

    float invN = 49.0f / (float)ncells;  // 1 / batch

    // Zero the 4-byte output, then accumulate into it with REDs.
    cudaMemsetAsync(d_out, 0, sizeof(float), 0);
    yolo_kernel<<<nblocks, TPB>>>(predict, label, ncells, invN, out);
}

// round 12
// speedup vs baseline: 1.2340x; 1.0239x over previous
#include <cuda_runtime.h>

#define TPB 256

__device__ __forceinline__ float compute_iou(float bx, float by, float bw, float bh,
                                             float lx, float ly, float lw, float lh) {
    const float invS = 1.0f / 7.0f;
    float x1 = bx * invS - bw * 0.5f;
    float y1 = by * invS - bh * 0.5f;
    float x2 = bx * invS + bw * 0.5f;
    float y2 = by * invS + bh * 0.5f;
    float u1 = lx * invS - lw * 0.5f;
    float v1 = ly * invS - lh * 0.5f;
    float u2 = lx * invS + lw * 0.5f;
    float v2 = ly * invS + lh * 0.5f;
    float a1 = (x2 - x1) * (y2 - y1);
    float a2 = (u2 - u1) * (v2 - v1);
    float left   = fmaxf(x1, u1);
    float right  = fminf(x2, u2);
    float top    = fmaxf(y1, v1);
    float bottom = fminf(y2, v2);
    bool valid = (left < right) && (top < bottom);
    float inter = valid ? (right - left) * (bottom - top) : 0.0f;
    float uni = a1 + a2 - inter;
    return valid ? (inter / uni) : 0.0f;
}

// Cold path (~4% of cells). __noinline__ keeps its register pressure out of
// the hot path's allocation; any spills are local to these rare calls.
__device__ __noinline__ float coord_cell_loss(const float* __restrict__ pbase,
                                              const float* __restrict__ lbase,
                                              float p4, float p9) {
    const float2* pp = reinterpret_cast<const float2*>(pbase);
    const float2* lp = reinterpret_cast<const float2*>(lbase);

    float2 p01 = __ldg(pp + 0);
    float2 p23 = __ldg(pp + 1);
    float2 p45 = __ldg(pp + 2);
    float2 p67 = __ldg(pp + 3);
    float2 p89 = __ldg(pp + 4);
    float2 l01 = __ldg(lp + 0);
    float2 l23 = __ldg(lp + 1);

    float cls = 0.0f;
#pragma unroll
    for (int j = 5; j < 13; j++) {
        float2 pv = __ldg(pp + j);
        float2 lv = __ldg(lp + j);
        float dx = pv.x - lv.x;
        float dy = pv.y - lv.y;
        cls += dx * dx + dy * dy;
    }

    float iou1 = compute_iou(p01.x, p01.y, p23.x, p23.y,
                             l01.x, l01.y, l23.x, l23.y);
    float iou2 = compute_iou(p45.y, p67.x, p67.y, p89.x,
                             l01.x, l01.y, l23.x, l23.y);
    bool pick1 = iou1 > iou2;

    float s0 = pick1 ? p01.x : p45.y;
    float s1 = pick1 ? p01.y : p67.x;
    float s2 = pick1 ? p23.x : p67.y;
    float s3 = pick1 ? p23.y : p89.x;

    float d0 = s0 - l01.x;
    float d1 = s1 - l01.y;
    float d2 = sqrtf(s2) - sqrtf(l23.x);
    float d3 = sqrtf(s3) - sqrtf(l23.y);
    float coord_cell = d0 * d0 + d1 * d1 + d2 * d2 + d3 * d3;

    float c  = pick1 ? p4 : p9;
    float io = pick1 ? iou1 : iou2;
    float dc = c - io;
    float obj_c_cell = dc * dc;

    float other = pick1 ? p9 : p4;
    float noobj_extra = other * other;

    return 5.0f * coord_cell + obj_c_cell + 0.5f * noobj_extra + cls;
}

__global__ void __launch_bounds__(TPB, 8)
yolo_kernel(const float* __restrict__ predict,
            const float* __restrict__ label,
            int ncells, float invN,
            float* __restrict__ out) {
    const int tid = threadIdx.x;
    int cell = blockIdx.x * TPB + tid;
    float loss = 0.0f;

    if (cell < ncells) {
        const float* pbase = predict + (size_t)cell * 26;
        const float* lbase = label   + (size_t)cell * 26;

        float l4 = __ldg(lbase + 4);
        float p4 = __ldg(pbase + 4);
        float p9 = __ldg(pbase + 9);

        if (l4 == 0.0f) {
            // noobj cell (~96%) — hot path, minimal registers
            loss = 0.5f * (p4 * p4 + p9 * p9);
        } else {
            loss = coord_cell_loss(pbase, lbase, p4, p9);
        }
    }

    // ---- block reduction ----
    __shared__ float sm[TPB / 32];
    float s = loss;
#pragma unroll
    for (int o = 16; o > 0; o >>= 1)
        s += __shfl_down_sync(0xFFFFFFFFu, s, o);
    if ((tid & 31) == 0)
        sm[tid >> 5] = s;
    __syncthreads();
    if (tid < 32) {
        s = (tid < (TPB / 32)) ? sm[tid] : 0.0f;
#pragma unroll
        for (int o = 16; o > 0; o >>= 1)
            s += __shfl_down_sync(0xFFFFFFFFu, s, o);
        if (tid == 0) {
            // Fire-and-forget no-return reduction into pre-zeroed out[0].
            float contrib = s * invN;
            asm volatile("red.relaxed.gpu.global.add.f32 [%0], %1;"
                         :: "l"(out), "f"(contrib) : "memory");
        }
    }
}

extern "C" void kernel_launch(void* const* d_in, const int* in_sizes, int n_in,
                              void* d_out, int out_size) {
    const float* predict = (const float*)d_in[0];
    const float* label   = (const float*)d_in[1];
    float* out = (float*)d_out;

    int total  = in_sizes[0];          // B*7*7*26
    int ncells = total / 26;           // B*49
    int nblocks = (ncells + TPB - 1) / TPB;

    float invN = 49.0f / (float)ncells;  // 1 / batch

    cudaMemsetAsync(d_out, 0, sizeof(float), 0);
    yolo_kernel<<<nblocks, TPB>>>(predict, label, ncells, invN, out);
}